// round 1
// baseline (speedup 1.0000x reference)
#include <cuda_runtime.h>

#define SITES 784
#define BOND  64
#define PHYS  2
#define NCLS  10
#define SPC   32          // samples per CTA
#define NTHREADS 256

#define A_SITE_FLOATS  (BOND*PHYS*BOND)      // 8192 floats per site (raw)
#define AD_SITE_FLOATS (BOND*PHYS*2*BOND)    // 16384 floats per site (duplicated pairs)

// Pre-duplicated A: ad[i][l][p][2d+e] = A[i][l][p][d]  (e=0,1)
__device__ float g_A_dup[(size_t)SITES * AD_SITE_FLOATS];

typedef unsigned long long u64;

__device__ __forceinline__ u64 fma2(u64 a, u64 b, u64 c) {
    u64 d;
    asm("fma.rn.f32x2 %0, %1, %2, %3;" : "=l"(d) : "l"(a), "l"(b), "l"(c));
    return d;
}
__device__ __forceinline__ u64 mul2(u64 a, u64 b) {
    u64 d;
    asm("mul.rn.f32x2 %0, %1, %2;" : "=l"(d) : "l"(a), "l"(b));
    return d;
}
__device__ __forceinline__ u64 pack2(float lo, float hi) {
    u64 d;
    asm("mov.b64 %0, {%1, %2};" : "=l"(d) : "f"(lo), "f"(hi));
    return d;
}
__device__ __forceinline__ void cpa16(float* s, const float* g) {
    unsigned sa = (unsigned)__cvta_generic_to_shared(s);
    asm volatile("cp.async.cg.shared.global [%0], [%1], 16;" :: "r"(sa), "l"(g));
}
__device__ __forceinline__ void cpa8(float* s, const float* g) {
    unsigned sa = (unsigned)__cvta_generic_to_shared(s);
    asm volatile("cp.async.ca.shared.global [%0], [%1], 8;" :: "r"(sa), "l"(g));
}

// ---------------------------------------------------------------------------
// Prep: duplicate each A element into an adjacent pair so the main loop's
// f32x2 FMAs can load broadcast-pairs directly with LDS.128 (no MOV packing).
// in float2 j -> out float4 {x,x,y,y} at 4j. (dup[2f]=dup[2f+1]=A[f], 2*(2j)=4j)
// ---------------------------------------------------------------------------
__global__ void prep_dup_kernel(const float* __restrict__ A, long n2) {
    long j = (long)blockIdx.x * blockDim.x + threadIdx.x;
    if (j < n2) {
        float2 v = ((const float2*)A)[j];
        ((float4*)g_A_dup)[j] = make_float4(v.x, v.x, v.y, v.y);
    }
}

// ---------------------------------------------------------------------------
// Main MPS chain kernel.
// smem: sA[3][16384] (dup A, triple-buffered cp.async pipeline)
//       sL[3][64][32] (left vectors, [l][s], triple-buffered)
//       sX[3][32][2]  (x per site per sample)
// Thread (dg = tid>>3, sg = tid&7) owns d = {2dg, 2dg+1}, s = {4sg..4sg+3}.
// Per l: 3x LDS.128, 8x fma.rn.f32x2 (16 FMA).
// ---------------------------------------------------------------------------
__global__ __launch_bounds__(NTHREADS, 1)
void mps_chain_kernel(const float* __restrict__ x,
                      const float* __restrict__ W,
                      const float* __restrict__ bvec,
                      float* __restrict__ out,
                      int batch) {
    extern __shared__ float smem[];
    float* sA = smem;                          // 3 * 16384 floats
    float* sL = sA + 3 * AD_SITE_FLOATS;       // 3 * 2048 floats
    float* sX = sL + 3 * (BOND * SPC);         // 3 * 64 floats

    const int tid = threadIdx.x;
    const int sg  = tid & 7;
    const int dg  = tid >> 3;
    const int s0  = sg * 4;
    const int sbase = blockIdx.x * SPC;

    // Prologue: prefetch sites 0 and 1
    for (int st = 0; st < 2; st++) {
        const float* gA = g_A_dup + (size_t)st * AD_SITE_FLOATS;
        float* dA = sA + st * AD_SITE_FLOATS;
        #pragma unroll
        for (int k = 0; k < AD_SITE_FLOATS / 4; k += NTHREADS)
            cpa16(dA + (size_t)(k + tid) * 4, gA + (size_t)(k + tid) * 4);
        if (tid < SPC) {
            int s = sbase + tid; if (s >= batch) s = batch - 1;
            cpa8(sX + st * (2 * SPC) + tid * 2, x + ((size_t)s * SITES + st) * 2);
        }
        asm volatile("cp.async.commit_group;" ::: "memory");
    }

    // init left buffer 0: left[l][s] = (l==0) ? 1 : 0
    for (int k = tid; k < BOND * SPC; k += NTHREADS)
        sL[k] = (k < SPC) ? 1.0f : 0.0f;

    int finbuf = SITES % 3;  // buffer holding final left if loop runs to completion

    for (int i = 0; i < SITES; i++) {
        const int ab = i % 3;
        asm volatile("cp.async.wait_group 1;" ::: "memory");
        __syncthreads();

        // prefetch site i+2 into buffer (i+2)%3 (its last readers finished 2 barriers ago)
        int pf = i + 2;
        if (pf < SITES) {
            int pb = pf % 3;
            const float* gA = g_A_dup + (size_t)pf * AD_SITE_FLOATS;
            float* dA = sA + pb * AD_SITE_FLOATS;
            #pragma unroll
            for (int k = 0; k < AD_SITE_FLOATS / 4; k += NTHREADS)
                cpa16(dA + (size_t)(k + tid) * 4, gA + (size_t)(k + tid) * 4);
            if (tid < SPC) {
                int s = sbase + tid; if (s >= batch) s = batch - 1;
                cpa8(sX + pb * (2 * SPC) + tid * 2, x + ((size_t)s * SITES + pf) * 2);
            }
        }
        asm volatile("cp.async.commit_group;" ::: "memory");

        // ---- compute: acc[p][dj][spair] over l ----
        const float* sAb = sA + ab * AD_SITE_FLOATS;
        const char*  sLb = (const char*)(sL + ab * (BOND * SPC));
        u64 acc000 = 0, acc001 = 0, acc010 = 0, acc011 = 0;
        u64 acc100 = 0, acc101 = 0, acc110 = 0, acc111 = 0;

        #pragma unroll 4
        for (int l = 0; l < BOND; l++) {
            // left[l][s0..s3] -> two f32x2 pairs
            ulonglong2 lv = *(const ulonglong2*)(sLb + (size_t)l * (SPC * 4) + s0 * 4);
            // dup A: [l][p][4dg .. 4dg+3] = {(a[d0],a[d0]),(a[d1],a[d1])}
            const char* ap = (const char*)sAb + (size_t)l * (2 * 2 * BOND * 4) + dg * 16;
            ulonglong2 a0 = *(const ulonglong2*)(ap);
            ulonglong2 a1 = *(const ulonglong2*)(ap + 2 * BOND * 4);

            acc000 = fma2(a0.x, lv.x, acc000);
            acc001 = fma2(a0.x, lv.y, acc001);
            acc010 = fma2(a0.y, lv.x, acc010);
            acc011 = fma2(a0.y, lv.y, acc011);
            acc100 = fma2(a1.x, lv.x, acc100);
            acc101 = fma2(a1.x, lv.y, acc101);
            acc110 = fma2(a1.y, lv.x, acc110);
            acc111 = fma2(a1.y, lv.y, acc111);
        }

        // ---- combine with x: left_new = x0*acc_p0 + x1*acc_p1 ----
        const float2* xb = (const float2*)(sX + ab * (2 * SPC));
        float2 xs0 = xb[s0 + 0], xs1 = xb[s0 + 1], xs2 = xb[s0 + 2], xs3 = xb[s0 + 3];
        u64 x0a = pack2(xs0.x, xs1.x), x0b = pack2(xs2.x, xs3.x);
        u64 x1a = pack2(xs0.y, xs1.y), x1b = pack2(xs2.y, xs3.y);

        u64 n00 = fma2(x0a, acc000, mul2(x1a, acc100));  // d0, s0s1
        u64 n01 = fma2(x0b, acc001, mul2(x1b, acc101));  // d0, s2s3
        u64 n10 = fma2(x0a, acc010, mul2(x1a, acc110));  // d1, s0s1
        u64 n11 = fma2(x0b, acc011, mul2(x1b, acc111));  // d1, s2s3

        float* sLw = sL + ((i + 1) % 3) * (BOND * SPC);
        *(ulonglong2*)(sLw + (2 * dg)     * SPC + s0) = make_ulonglong2(n00, n01);
        *(ulonglong2*)(sLw + (2 * dg + 1) * SPC + s0) = make_ulonglong2(n10, n11);

        // ---- early exit: once left is exactly (+/-)0 everywhere, the rest of
        // the chain is exactly zero and logits reduce to b. Bit-exact shortcut.
        if ((i & 7) == 7) {
            u64 m = (n00 | n01 | n10 | n11) & 0x7FFFFFFF7FFFFFFFull;
            if (__syncthreads_and(m == 0)) { finbuf = (i + 1) % 3; break; }
        }
    }

    asm volatile("cp.async.wait_group 0;" ::: "memory");
    __syncthreads();

    // epilogue: final right bond dim is 1 -> logits = left[d=0] * W[0,:] + b
    const float* Lf = sL + finbuf * (BOND * SPC);   // row d=0 is Lf[0..31]
    for (int idx = tid; idx < SPC * NCLS; idx += NTHREADS) {
        int s = idx / NCLS, c = idx % NCLS;
        int gs = sbase + s;
        if (gs < batch)
            out[(size_t)gs * NCLS + c] = fmaf(Lf[s], W[c], bvec[c]);
    }
}

extern "C" void kernel_launch(void* const* d_in, const int* in_sizes, int n_in,
                              void* d_out, int out_size) {
    const float* x = (const float*)d_in[0];   // [batch, 784, 2]
    const float* A = (const float*)d_in[1];   // [784, 64, 2, 64]
    const float* W = (const float*)d_in[2];   // [1, 10]
    const float* b = (const float*)d_in[3];   // [10]
    float* out = (float*)d_out;

    int batch = in_sizes[0] / (SITES * PHYS);

    // 1) duplicate A into broadcast-pair layout (deterministic every launch)
    long n2 = (long)SITES * A_SITE_FLOATS / 2;          // float2 count
    int pblocks = (int)((n2 + 255) / 256);
    prep_dup_kernel<<<pblocks, 256>>>(A, n2);

    // 2) chain kernel
    size_t smem_bytes = (size_t)(3 * AD_SITE_FLOATS + 3 * BOND * SPC + 3 * 2 * SPC) * sizeof(float);
    cudaFuncSetAttribute(mps_chain_kernel,
                         cudaFuncAttributeMaxDynamicSharedMemorySize, (int)smem_bytes);
    int grid = (batch + SPC - 1) / SPC;
    mps_chain_kernel<<<grid, NTHREADS, smem_bytes>>>(x, W, b, out, batch);
}